// round 6
// baseline (speedup 1.0000x reference)
#include <cuda_runtime.h>
#include <math.h>

#define N_NODES 4096
#define N_EDGES 8192
#define DIMQ    4096

// ---------------- device scratch (no allocations allowed) ----------------
__device__ float g_boT[4 * N_EDGES];   // bo transposed [f][j], ref f32 semantics
__device__ float g_biT[4 * N_EDGES];
__device__ float g_mi[N_NODES * 4];
__device__ float g_mo[N_NODES * 4];
__device__ float g_cs[33];
__device__ float g_sn[33];

// ---------------- cp.async helpers ----------------
__device__ __forceinline__ unsigned smem_u32(const void* p) {
    return (unsigned)__cvta_generic_to_shared(p);
}
__device__ __forceinline__ void cp_async16(void* dst, const void* src) {
    asm volatile("cp.async.cg.shared.global [%0], [%1], 16;"
                 :: "r"(smem_u32(dst)), "l"(src));
}
__device__ __forceinline__ void cp_commit() {
    asm volatile("cp.async.commit_group;");
}
template<int N> __device__ __forceinline__ void cp_wait() {
    asm volatile("cp.async.wait_group %0;" :: "n"(N));
}

// ---------------- init: precompute theta trig ----------------
__global__ void init_kernel(const float* __restrict__ theta) {
    int i = threadIdx.x;
    if (i < 33) {
        double h = 0.5 * (double)theta[i];
        g_cs[i] = (float)cos(h);
        g_sn[i] = (float)sin(h);
    }
}

// ---------------- phase 1: bo = Ro^T X, bi = Ri^T X ----------------
// Reference f32 semantics (hypothesis: XLA materializes the transpose, then
// runs the SAME VF=4 dot emitter proven for phase 2):
//   per output (j,f): 4 lanes over n == l (mod 4), ascending,
//   acc_l = fma(Ro[n,j], X[n,f], acc_l); combine ((l0+l1)+(l2+l3)).
// Thread owns (j,f): tid = [jl:5][f:2]; 32 j per block, 512 blocks.
#define P1_BJ 32
__global__ void __launch_bounds__(128) phase1_kernel(const float* __restrict__ Ri,
                                                     const float* __restrict__ Ro,
                                                     const float* __restrict__ X) {
    int mat = blockIdx.x & 1;
    const float* A = mat ? Ri : Ro;
    float* dst     = mat ? g_biT : g_boT;
    int tid = threadIdx.x;
    int f  = tid & 3;
    int jl = tid >> 2;                           // 0..31
    int j  = (int)(blockIdx.x >> 1) * P1_BJ + jl;

    __shared__ float xs[256][4];                 // one 256-row tile of X

    float a0 = 0.f, a1 = 0.f, a2 = 0.f, a3 = 0.f;
    const float* col = A + j;
    const float4* X4 = (const float4*)X;

    for (int t = 0; t < N_NODES / 256; t++) {    // 16 tiles
        int n0 = t * 256;
        for (int i = tid; i < 256; i += 128)
            *(float4*)&xs[i][0] = __ldg(&X4[n0 + i]);
        __syncthreads();

        const float* c0 = col + (size_t)n0 * N_EDGES;
        #pragma unroll 4
        for (int r4 = 0; r4 < 64; r4++) {
            float v0 = c0[(size_t)(r4 * 4 + 0) * N_EDGES];
            float v1 = c0[(size_t)(r4 * 4 + 1) * N_EDGES];
            float v2 = c0[(size_t)(r4 * 4 + 2) * N_EDGES];
            float v3 = c0[(size_t)(r4 * 4 + 3) * N_EDGES];
            a0 = __fmaf_rn(v0, xs[r4 * 4 + 0][f], a0);
            a1 = __fmaf_rn(v1, xs[r4 * 4 + 1][f], a1);
            a2 = __fmaf_rn(v2, xs[r4 * 4 + 2][f], a2);
            a3 = __fmaf_rn(v3, xs[r4 * 4 + 3][f], a3);
        }
        __syncthreads();
    }
    // adjacent pairwise combine: ((l0+l1)+(l2+l3))
    float x = __fadd_rn(__fadd_rn(a0, a1), __fadd_rn(a2, a3));
    dst[(size_t)f * N_EDGES + j] = x;
}

// ---------------- phase 2: mi = (Ri.*e) @ bo, mo = (Ro.*e) @ bi ----------------
// Reference f32 semantics (confirmed, corr 0.96): 4-lane mod-4 interleaved
// ascending FMA chains over j, term = fl32(Ri[n,j]*e[j]) (materialized mul),
// combined ((l0+l1)+(l2+l3)). One thread owns (n, f): 4 lane accumulators.
#define P2_NB  32
#define P2_JT  128
#define P2_PAD 4
__global__ void __launch_bounds__(128) phase2_kernel(const float* __restrict__ Ri,
                                                     const float* __restrict__ Ro,
                                                     const float* __restrict__ e) {
    int mat = blockIdx.x & 1;            // 0: mi (Ri, boT), 1: mo (Ro, biT)
    const float* A  = mat ? Ro : Ri;
    const float* BT = mat ? g_biT : g_boT;
    float* dst      = mat ? g_mo : g_mi;
    int n0  = (int)(blockIdx.x >> 1) * P2_NB;
    int tid = threadIdx.x;
    int f = tid & 3, nl = tid >> 2;
    int n = n0 + nl;

    __shared__ float tile[2][P2_NB][P2_JT + P2_PAD];

    auto stage = [&](int t, int s) {
        int jt = t * P2_JT;
        const float* base = A + (size_t)n0 * N_EDGES + jt;
        #pragma unroll
        for (int o = 0; o < 8; o++) {
            int idx = o * 128 + tid;          // float4 index in [0, 1024)
            int row = idx >> 5, c4 = idx & 31;
            cp_async16(&tile[s][row][c4 * 4], base + (size_t)row * N_EDGES + c4 * 4);
        }
        cp_commit();
    };

    stage(0, 0);
    float a0 = 0.f, a1 = 0.f, a2 = 0.f, a3 = 0.f;
    const float4* e4p = (const float4*)e;
    const float4* bt4 = (const float4*)(BT + (size_t)f * N_EDGES);
    const int NT = N_EDGES / P2_JT;     // 64
    for (int t = 0; t < NT; t++) {
        int s = t & 1;
        if (t + 1 < NT) { stage(t + 1, s ^ 1); cp_wait<1>(); }
        else            { cp_wait<0>(); }
        __syncthreads();
        int ib = t * (P2_JT / 4);
        #pragma unroll
        for (int q = 0; q < P2_JT / 4; q++) {
            float4 av = *(const float4*)&tile[s][nl][q * 4];
            float4 ev = __ldg(&e4p[ib + q]);
            float4 bv = __ldg(&bt4[ib + q]);
            a0 = __fmaf_rn(__fmul_rn(av.x, ev.x), bv.x, a0);
            a1 = __fmaf_rn(__fmul_rn(av.y, ev.y), bv.y, a1);
            a2 = __fmaf_rn(__fmul_rn(av.z, ev.z), bv.z, a2);
            a3 = __fmaf_rn(__fmul_rn(av.w, ev.w), bv.w, a3);
        }
        __syncthreads();
    }
    // adjacent pairwise combine: ((l0+l1)+(l2+l3))
    float x = __fadd_rn(__fadd_rn(a0, a1), __fadd_rn(a2, a3));
    dst[n * 4 + f] = x;
}

// ---------------- circuit: 12-wire statevector per node in smem ----------------
// wire w <-> bit (11 - w) of the amplitude index.
__global__ void __launch_bounds__(256) circuit_kernel(const float* __restrict__ X,
                                                      float* __restrict__ out) {
    __shared__ float  st[DIMQ];
    __shared__ float  cw[12], sw[12];
    __shared__ float  cst[33], snt[33];
    __shared__ double redsm[8];

    int b = blockIdx.x, tid = threadIdx.x;

    if (tid < 12) {
        // angle is the reference's f32 value; trig in f64 (exact range reduction
        // for |ang| up to ~1e5), rounded to f32 — matches libm cosf to ~1 ulp.
        float angf = (tid < 4) ? g_mi[b * 4 + tid]
                   : (tid < 8) ? g_mo[b * 4 + tid - 4]
                               : X[b * 4 + tid - 8];
        double h = 0.5 * (double)angf;
        cw[tid] = (float)cos(h);
        sw[tid] = (float)sin(h);
    }
    if (tid < 33) { cst[tid] = g_cs[tid]; snt[tid] = g_sn[tid]; }
    __syncthreads();

    // Initial product state: amp[x] = prod_w (bit_{11-w}(x) ? sin : cos)
    float cr[12], sr[12];
    #pragma unroll
    for (int w = 0; w < 12; w++) { cr[w] = cw[w]; sr[w] = sw[w]; }
    #pragma unroll
    for (int k0 = 0; k0 < 16; k0++) {
        int k = k0 * 256 + tid;
        float p = 1.0f;
        #pragma unroll
        for (int w = 0; w < 12; w++) p *= ((k >> (11 - w)) & 1) ? sr[w] : cr[w];
        st[k] = p;
    }
    __syncthreads();

#define GRY(TI, WIRE) {                                                     \
    const int bb_ = 11 - (WIRE);                                            \
    const float c_ = cst[TI], s_ = snt[TI];                                 \
    _Pragma("unroll")                                                       \
    for (int q_ = 0; q_ < 8; q_++) {                                        \
        int p_  = q_ * 256 + tid;                                           \
        int i0_ = ((p_ >> bb_) << (bb_ + 1)) | (p_ & ((1 << bb_) - 1));     \
        int i1_ = i0_ | (1 << bb_);                                         \
        float a0_ = st[i0_], a1_ = st[i1_];                                 \
        st[i0_] = c_ * a0_ - s_ * a1_;                                      \
        st[i1_] = s_ * a0_ + c_ * a1_;                                      \
    }                                                                       \
    __syncthreads(); }

#define GCX(CTRL, TGT) {                                                    \
    const int cb_ = 11 - (CTRL), tb_ = 11 - (TGT);                          \
    const int lo_ = cb_ < tb_ ? cb_ : tb_;                                  \
    const int hi_ = cb_ < tb_ ? tb_ : cb_;                                  \
    _Pragma("unroll")                                                       \
    for (int q_ = 0; q_ < 4; q_++) {                                        \
        int p_ = q_ * 256 + tid;                                            \
        int x_ = (p_ & ((1 << lo_) - 1)) | ((p_ >> lo_) << (lo_ + 1));      \
        int y_ = (x_ & ((1 << hi_) - 1)) | ((x_ >> hi_) << (hi_ + 1));      \
        int ia_ = y_ | (1 << cb_);                                          \
        int ib_ = ia_ | (1 << tb_);                                         \
        float t_ = st[ia_]; st[ia_] = st[ib_]; st[ib_] = t_;                \
    }                                                                       \
    __syncthreads(); }

    GRY(0,1)  GRY(1,2)   GCX(1,2)   GRY(2,3)  GRY(3,4)   GCX(4,3)
    GRY(4,5)  GRY(5,6)   GCX(5,6)   GRY(6,7)  GRY(7,8)   GCX(7,8)
    GRY(8,9)  GRY(9,10)  GCX(10,9)  GRY(10,0) GRY(11,1)  GCX(0,1)
    GRY(12,2) GRY(13,3)  GCX(3,2)   GRY(14,4) GRY(15,5)  GCX(4,5)
    GRY(16,6) GRY(17,7)  GCX(7,6)   GRY(18,8) GRY(19,9)  GCX(8,9)
    GRY(20,10) GRY(21,11) GCX(11,10) GRY(22,2) GRY(23,5) GCX(5,2)
    GRY(24,6) GRY(25,9)  GCX(6,9)   GRY(26,1) GRY(27,2)  GCX(1,2)
    GRY(28,9) GRY(29,10) GCX(10,9)  GRY(30,2) GRY(31,9)  GCX(2,9)
    GRY(32,9)

#undef GRY
#undef GCX

    // expz = sum_{bit2=0} amp^2 - sum_{bit2=1} amp^2  (wire 9 -> bit 2)
    float local = 0.0f;
    #pragma unroll
    for (int k0 = 0; k0 < 16; k0++) {
        int k = k0 * 256 + tid;
        float v = st[k];
        float v2 = v * v;
        local += ((k >> 2) & 1) ? -v2 : v2;
    }
    double dv = (double)local;
    #pragma unroll
    for (int o = 16; o > 0; o >>= 1) dv += __shfl_down_sync(0xffffffffu, dv, o);
    int lane = tid & 31, wp = tid >> 5;
    if (lane == 0) redsm[wp] = dv;
    __syncthreads();
    if (tid == 0) {
        double expz = 0.0;
        for (int w = 0; w < 8; w++) expz += redsm[w];
        out[b] = (float)(1.5707963267948966 * (1.0 - expz));
    }
}

// ---------------- launch ----------------
extern "C" void kernel_launch(void* const* d_in, const int* in_sizes, int n_in,
                              void* d_out, int out_size) {
    // Robust mapping by element counts (dict order: X, e, Ri, Ro, theta_learn)
    const float *X = 0, *e = 0, *Ri = 0, *Ro = 0, *th = 0;
    for (int i = 0; i < n_in; i++) {
        int s = in_sizes[i];
        const float* p = (const float*)d_in[i];
        if (s == N_NODES * 4)            X = p;
        else if (s == N_EDGES)           e = p;
        else if (s == 33)                th = p;
        else if (s == N_NODES * N_EDGES) { if (!Ri) Ri = p; else Ro = p; }
    }
    float* out = (float*)d_out;

    init_kernel<<<1, 64>>>(th);
    phase1_kernel<<<(N_EDGES / P1_BJ) * 2, 128>>>(Ri, Ro, X);
    phase2_kernel<<<(N_NODES / P2_NB) * 2, 128>>>(Ri, Ro, e);
    circuit_kernel<<<N_NODES, 256>>>(X, out);
}

// round 7
// speedup vs baseline: 1.7644x; 1.7644x over previous
#include <cuda_runtime.h>
#include <math.h>

#define N_NODES 4096
#define N_EDGES 8192
#define DIMQ    4096

// ---------------- device scratch (no allocations allowed) ----------------
__device__ float g_boT[4 * N_EDGES];   // bo transposed [f][j], ref f32 semantics
__device__ float g_biT[4 * N_EDGES];
__device__ float g_mi[N_NODES * 4];
__device__ float g_mo[N_NODES * 4];
__device__ float g_cs[33];
__device__ float g_sn[33];

// ---------------- cp.async helpers ----------------
__device__ __forceinline__ unsigned smem_u32(const void* p) {
    return (unsigned)__cvta_generic_to_shared(p);
}
__device__ __forceinline__ void cp_async16(void* dst, const void* src) {
    asm volatile("cp.async.cg.shared.global [%0], [%1], 16;"
                 :: "r"(smem_u32(dst)), "l"(src));
}
__device__ __forceinline__ void cp_commit() {
    asm volatile("cp.async.commit_group;");
}
template<int N> __device__ __forceinline__ void cp_wait() {
    asm volatile("cp.async.wait_group %0;" :: "n"(N));
}

// ---------------- init: precompute theta trig ----------------
__global__ void init_kernel(const float* __restrict__ theta) {
    int i = threadIdx.x;
    if (i < 33) {
        double h = 0.5 * (double)theta[i];
        g_cs[i] = (float)cos(h);
        g_sn[i] = (float)sin(h);
    }
}

// ---------------- phase 1: bo = Ro^T X, bi = Ri^T X ----------------
// Reference f32 semantics (CONFIRMED r6, rel_err 8.5e-8): per output (j,f),
// 4 lanes over n == l (mod 4) ascending, acc_l = fma(A[n,j], X[n,f], acc_l),
// combine ((l0+l1)+(l2+l3)).
// Coalesced: A staged in 64n x 64j smem tiles (cp.async, double buffered).
// Thread owns (j,f): tid = [jl:6][f:2]; 64 j per block, 256 blocks.
#define P1_BJ 64
#define P1_BN 64
__global__ void __launch_bounds__(256) phase1_kernel(const float* __restrict__ Ri,
                                                     const float* __restrict__ Ro,
                                                     const float* __restrict__ X) {
    int mat = blockIdx.x & 1;
    const float* A = mat ? Ri : Ro;
    float* dst     = mat ? g_biT : g_boT;
    int tid = threadIdx.x;
    int f  = tid & 3;
    int jl = tid >> 2;                           // 0..63
    int j0 = (int)(blockIdx.x >> 1) * P1_BJ;

    __shared__ float tile[2][P1_BN][P1_BJ];      // 2 x 16KB
    __shared__ float xs[2][P1_BN][4];            // 2 x 1KB

    auto stage = [&](int t, int s) {
        int n0 = t * P1_BN;
        const float* base = A + (size_t)n0 * N_EDGES + j0;
        #pragma unroll
        for (int o = 0; o < 4; o++) {
            int idx = o * 256 + tid;             // float4 idx in [0,1024)
            int row = idx >> 4, c4 = idx & 15;
            cp_async16(&tile[s][row][c4 * 4], base + (size_t)row * N_EDGES + c4 * 4);
        }
        if (tid < P1_BN)
            cp_async16(&xs[s][tid][0], X + (size_t)(n0 + tid) * 4);
        cp_commit();
    };

    stage(0, 0);
    float a0 = 0.f, a1 = 0.f, a2 = 0.f, a3 = 0.f;
    const int NT = N_NODES / P1_BN;              // 64
    for (int t = 0; t < NT; t++) {
        int s = t & 1;
        if (t + 1 < NT) { stage(t + 1, s ^ 1); cp_wait<1>(); }
        else            { cp_wait<0>(); }
        __syncthreads();
        #pragma unroll
        for (int r4 = 0; r4 < P1_BN / 4; r4++) {
            a0 = __fmaf_rn(tile[s][r4 * 4 + 0][jl], xs[s][r4 * 4 + 0][f], a0);
            a1 = __fmaf_rn(tile[s][r4 * 4 + 1][jl], xs[s][r4 * 4 + 1][f], a1);
            a2 = __fmaf_rn(tile[s][r4 * 4 + 2][jl], xs[s][r4 * 4 + 2][f], a2);
            a3 = __fmaf_rn(tile[s][r4 * 4 + 3][jl], xs[s][r4 * 4 + 3][f], a3);
        }
        __syncthreads();
    }
    // adjacent pairwise combine: ((l0+l1)+(l2+l3))
    float x = __fadd_rn(__fadd_rn(a0, a1), __fadd_rn(a2, a3));
    dst[(size_t)f * N_EDGES + j0 + jl] = x;
}

// ---------------- phase 2: mi = (Ri.*e) @ bo, mo = (Ro.*e) @ bi ----------------
// Reference f32 semantics (confirmed): 4-lane mod-4 interleaved ascending FMA
// chains over j, term = fl32(Ri[n,j]*e[j]), combined ((l0+l1)+(l2+l3)).
#define P2_NB  32
#define P2_JT  128
#define P2_PAD 4
__global__ void __launch_bounds__(128) phase2_kernel(const float* __restrict__ Ri,
                                                     const float* __restrict__ Ro,
                                                     const float* __restrict__ e) {
    int mat = blockIdx.x & 1;            // 0: mi (Ri, boT), 1: mo (Ro, biT)
    const float* A  = mat ? Ro : Ri;
    const float* BT = mat ? g_biT : g_boT;
    float* dst      = mat ? g_mo : g_mi;
    int n0  = (int)(blockIdx.x >> 1) * P2_NB;
    int tid = threadIdx.x;
    int f = tid & 3, nl = tid >> 2;
    int n = n0 + nl;

    __shared__ float tile[2][P2_NB][P2_JT + P2_PAD];

    auto stage = [&](int t, int s) {
        int jt = t * P2_JT;
        const float* base = A + (size_t)n0 * N_EDGES + jt;
        #pragma unroll
        for (int o = 0; o < 8; o++) {
            int idx = o * 128 + tid;          // float4 index in [0, 1024)
            int row = idx >> 5, c4 = idx & 31;
            cp_async16(&tile[s][row][c4 * 4], base + (size_t)row * N_EDGES + c4 * 4);
        }
        cp_commit();
    };

    stage(0, 0);
    float a0 = 0.f, a1 = 0.f, a2 = 0.f, a3 = 0.f;
    const float4* e4p = (const float4*)e;
    const float4* bt4 = (const float4*)(BT + (size_t)f * N_EDGES);
    const int NT = N_EDGES / P2_JT;     // 64
    for (int t = 0; t < NT; t++) {
        int s = t & 1;
        if (t + 1 < NT) { stage(t + 1, s ^ 1); cp_wait<1>(); }
        else            { cp_wait<0>(); }
        __syncthreads();
        int ib = t * (P2_JT / 4);
        #pragma unroll
        for (int q = 0; q < P2_JT / 4; q++) {
            float4 av = *(const float4*)&tile[s][nl][q * 4];
            float4 ev = __ldg(&e4p[ib + q]);
            float4 bv = __ldg(&bt4[ib + q]);
            a0 = __fmaf_rn(__fmul_rn(av.x, ev.x), bv.x, a0);
            a1 = __fmaf_rn(__fmul_rn(av.y, ev.y), bv.y, a1);
            a2 = __fmaf_rn(__fmul_rn(av.z, ev.z), bv.z, a2);
            a3 = __fmaf_rn(__fmul_rn(av.w, ev.w), bv.w, a3);
        }
        __syncthreads();
    }
    float x = __fadd_rn(__fadd_rn(a0, a1), __fadd_rn(a2, a3));
    dst[n * 4 + f] = x;
}

// ---------------- circuit: 12-wire statevector per node in smem ----------------
// wire w <-> bit (11 - w). Gates come as (RY,RY,CX) triples on two wires; each
// triple is a closed map on 4-amplitude groups -> one fused smem pass per triple
// (bitwise identical to sequential application of the three gates).
__global__ void __launch_bounds__(256) circuit_kernel(const float* __restrict__ X,
                                                      float* __restrict__ out) {
    __shared__ float  st[DIMQ];
    __shared__ float  cw[12], sw[12];
    __shared__ float  cst[33], snt[33];
    __shared__ double redsm[8];

    int b = blockIdx.x, tid = threadIdx.x;

    if (tid < 12) {
        float angf = (tid < 4) ? g_mi[b * 4 + tid]
                   : (tid < 8) ? g_mo[b * 4 + tid - 4]
                               : X[b * 4 + tid - 8];
        double h = 0.5 * (double)angf;   // f64 trig: exact range reduction
        cw[tid] = (float)cos(h);
        sw[tid] = (float)sin(h);
    }
    if (tid < 33) { cst[tid] = g_cs[tid]; snt[tid] = g_sn[tid]; }
    __syncthreads();

    // Initial product state: amp[x] = prod_w (bit_{11-w}(x) ? sin : cos)
    float cr[12], sr[12];
    #pragma unroll
    for (int w = 0; w < 12; w++) { cr[w] = cw[w]; sr[w] = sw[w]; }
    #pragma unroll
    for (int k0 = 0; k0 < 16; k0++) {
        int k = k0 * 256 + tid;
        float p = 1.0f;
        #pragma unroll
        for (int w = 0; w < 12; w++) p *= ((k >> (11 - w)) & 1) ? sr[w] : cr[w];
        st[k] = p;
    }
    __syncthreads();

// Fused RY(T1@W1) -> RY(T2@W2) -> CX; CW=0: ctrl=W1, CW=1: ctrl=W2.
#define FUSED(T1, W1, T2, W2, CW) {                                          \
    const int b1_ = 11 - (W1), b2_ = 11 - (W2);                              \
    const int lo_ = (b1_ < b2_) ? b1_ : b2_;                                 \
    const int hi_ = (b1_ < b2_) ? b2_ : b1_;                                 \
    const int m1_ = 1 << b1_, m2_ = 1 << b2_;                                \
    const float c1_ = cst[T1], s1_ = snt[T1];                                \
    const float c2_ = cst[T2], s2_ = snt[T2];                                \
    _Pragma("unroll")                                                        \
    for (int q_ = 0; q_ < 4; q_++) {                                         \
        int p_ = q_ * 256 + tid;                                             \
        int x_ = (p_ & ((1 << lo_) - 1)) | ((p_ >> lo_) << (lo_ + 1));       \
        int y_ = (x_ & ((1 << hi_) - 1)) | ((x_ >> hi_) << (hi_ + 1));       \
        float a00 = st[y_],        a10 = st[y_ | m1_];                       \
        float a01 = st[y_ | m2_],  a11 = st[y_ | m1_ | m2_];                 \
        float t00 = c1_ * a00 - s1_ * a10, t10 = s1_ * a00 + c1_ * a10;      \
        float t01 = c1_ * a01 - s1_ * a11, t11 = s1_ * a01 + c1_ * a11;      \
        float u00 = c2_ * t00 - s2_ * t01, u01 = s2_ * t00 + c2_ * t01;      \
        float u10 = c2_ * t10 - s2_ * t11, u11 = s2_ * t10 + c2_ * t11;      \
        if (CW == 0) { float tp = u10; u10 = u11; u11 = tp; }                \
        else         { float tp = u01; u01 = u11; u11 = tp; }                \
        st[y_]              = u00; st[y_ | m1_]       = u10;                 \
        st[y_ | m2_]        = u01; st[y_ | m1_ | m2_] = u11;                 \
    }                                                                        \
    __syncthreads(); }

#define GRY(TI, WIRE) {                                                     \
    const int bb_ = 11 - (WIRE);                                            \
    const float c_ = cst[TI], s_ = snt[TI];                                 \
    _Pragma("unroll")                                                       \
    for (int q_ = 0; q_ < 8; q_++) {                                        \
        int p_  = q_ * 256 + tid;                                           \
        int i0_ = ((p_ >> bb_) << (bb_ + 1)) | (p_ & ((1 << bb_) - 1));     \
        int i1_ = i0_ | (1 << bb_);                                         \
        float a0_ = st[i0_], a1_ = st[i1_];                                 \
        st[i0_] = c_ * a0_ - s_ * a1_;                                      \
        st[i1_] = s_ * a0_ + c_ * a1_;                                      \
    }                                                                       \
    __syncthreads(); }

    FUSED( 0, 1,  1, 2,  0)   // cx 1->2
    FUSED( 2, 3,  3, 4,  1)   // cx 4->3
    FUSED( 4, 5,  5, 6,  0)   // cx 5->6
    FUSED( 6, 7,  7, 8,  0)   // cx 7->8
    FUSED( 8, 9,  9, 10, 1)   // cx 10->9
    FUSED(10, 0, 11, 1,  0)   // cx 0->1
    FUSED(12, 2, 13, 3,  1)   // cx 3->2
    FUSED(14, 4, 15, 5,  0)   // cx 4->5
    FUSED(16, 6, 17, 7,  1)   // cx 7->6
    FUSED(18, 8, 19, 9,  0)   // cx 8->9
    FUSED(20, 10, 21, 11, 1)  // cx 11->10
    FUSED(22, 2, 23, 5,  1)   // cx 5->2
    FUSED(24, 6, 25, 9,  0)   // cx 6->9
    FUSED(26, 1, 27, 2,  0)   // cx 1->2
    FUSED(28, 9, 29, 10, 1)   // cx 10->9
    FUSED(30, 2, 31, 9,  0)   // cx 2->9
    GRY(32, 9)

#undef FUSED
#undef GRY

    // expz = sum_{bit2=0} amp^2 - sum_{bit2=1} amp^2  (wire 9 -> bit 2)
    float local = 0.0f;
    #pragma unroll
    for (int k0 = 0; k0 < 16; k0++) {
        int k = k0 * 256 + tid;
        float v = st[k];
        float v2 = v * v;
        local += ((k >> 2) & 1) ? -v2 : v2;
    }
    double dv = (double)local;
    #pragma unroll
    for (int o = 16; o > 0; o >>= 1) dv += __shfl_down_sync(0xffffffffu, dv, o);
    int lane = tid & 31, wp = tid >> 5;
    if (lane == 0) redsm[wp] = dv;
    __syncthreads();
    if (tid == 0) {
        double expz = 0.0;
        for (int w = 0; w < 8; w++) expz += redsm[w];
        out[b] = (float)(1.5707963267948966 * (1.0 - expz));
    }
}

// ---------------- launch ----------------
extern "C" void kernel_launch(void* const* d_in, const int* in_sizes, int n_in,
                              void* d_out, int out_size) {
    const float *X = 0, *e = 0, *Ri = 0, *Ro = 0, *th = 0;
    for (int i = 0; i < n_in; i++) {
        int s = in_sizes[i];
        const float* p = (const float*)d_in[i];
        if (s == N_NODES * 4)            X = p;
        else if (s == N_EDGES)           e = p;
        else if (s == 33)                th = p;
        else if (s == N_NODES * N_EDGES) { if (!Ri) Ri = p; else Ro = p; }
    }
    float* out = (float*)d_out;

    init_kernel<<<1, 64>>>(th);
    phase1_kernel<<<(N_EDGES / P1_BJ) * 2, 256>>>(Ri, Ro, X);
    phase2_kernel<<<(N_NODES / P2_NB) * 2, 128>>>(Ri, Ro, e);
    circuit_kernel<<<N_NODES, 256>>>(X, out);
}

// round 8
// speedup vs baseline: 4.2262x; 2.3952x over previous
#include <cuda_runtime.h>
#include <math.h>

#define N_NODES 4096
#define N_EDGES 8192
#define DIMQ    4096

// ---------------- device scratch (no allocations allowed) ----------------
__device__ float g_boT[4 * N_EDGES];   // bo transposed [f][j], ref f32 semantics
__device__ float g_biT[4 * N_EDGES];
__device__ float g_mi[N_NODES * 4];
__device__ float g_mo[N_NODES * 4];
__device__ float g_cs[33];
__device__ float g_sn[33];

// ---------------- cp.async helpers ----------------
__device__ __forceinline__ unsigned smem_u32(const void* p) {
    return (unsigned)__cvta_generic_to_shared(p);
}
__device__ __forceinline__ void cp_async16(void* dst, const void* src) {
    asm volatile("cp.async.cg.shared.global [%0], [%1], 16;"
                 :: "r"(smem_u32(dst)), "l"(src));
}
__device__ __forceinline__ void cp_commit() {
    asm volatile("cp.async.commit_group;");
}
template<int N> __device__ __forceinline__ void cp_wait() {
    asm volatile("cp.async.wait_group %0;" :: "n"(N));
}

// ---------------- init: precompute theta trig ----------------
__global__ void init_kernel(const float* __restrict__ theta) {
    int i = threadIdx.x;
    if (i < 33) {
        double h = 0.5 * (double)theta[i];
        g_cs[i] = (float)cos(h);
        g_sn[i] = (float)sin(h);
    }
}

// ---------------- phase 1: bo = Ro^T X, bi = Ri^T X ----------------
// Ref semantics (confirmed r6): per (j,f), 4 lanes over n==l (mod 4) ascending,
// acc_l = fma(A[n,j], X[n,f], acc_l); combine ((l0+l1)+(l2+l3)).
// Thread = (jl, l): warp l, lane jl; 4 f-accumulators; 1 LDS + 1 LDS128 + 4 FMA per n.
#define P1_BJ 32
#define P1_BN 128
#define P1_LD 36
__global__ void __launch_bounds__(128) phase1_kernel(const float* __restrict__ Ri,
                                                     const float* __restrict__ Ro,
                                                     const float* __restrict__ X) {
    int mat = blockIdx.x & 1;
    const float* A = mat ? Ri : Ro;
    float* dst     = mat ? g_biT : g_boT;
    int j0  = (int)(blockIdx.x >> 1) * P1_BJ;
    int tid = threadIdx.x;
    int jl = tid & 31, l = tid >> 5;             // warp = lane index l

    __shared__ __align__(16) float  tile[2][P1_BN][P1_LD];
    __shared__ float4 xs[2][P1_BN];
    __shared__ float  pacc[4][4][32];            // [l][f][jl]

    auto stage = [&](int t, int s) {
        int n0 = t * P1_BN;
        const float* base = A + (size_t)n0 * N_EDGES + j0;
        #pragma unroll
        for (int o = 0; o < 8; o++) {
            int idx = o * 128 + tid;             // 1024 float4
            int row = idx >> 3, c4 = idx & 7;
            cp_async16(&tile[s][row][c4 * 4], base + (size_t)row * N_EDGES + c4 * 4);
        }
        cp_async16(&xs[s][tid], X + (size_t)(n0 + tid) * 4);
        cp_commit();
    };

    stage(0, 0);
    float a0 = 0.f, a1 = 0.f, a2 = 0.f, a3 = 0.f;
    const int NT = N_NODES / P1_BN;              // 32
    for (int t = 0; t < NT; t++) {
        int s = t & 1;
        if (t + 1 < NT) { stage(t + 1, s ^ 1); cp_wait<1>(); }
        else            { cp_wait<0>(); }
        __syncthreads();
        #pragma unroll 8
        for (int i = 0; i < P1_BN / 4; i++) {
            int row = i * 4 + l;
            float  a = tile[s][row][jl];
            float4 x = xs[s][row];
            a0 = __fmaf_rn(a, x.x, a0);
            a1 = __fmaf_rn(a, x.y, a1);
            a2 = __fmaf_rn(a, x.z, a2);
            a3 = __fmaf_rn(a, x.w, a3);
        }
        __syncthreads();
    }
    pacc[l][0][jl] = a0; pacc[l][1][jl] = a1;
    pacc[l][2][jl] = a2; pacc[l][3][jl] = a3;
    __syncthreads();
    // finalize: thread (f=l, jl): combine ((l0+l1)+(l2+l3))
    {
        int f = l;
        float x = __fadd_rn(__fadd_rn(pacc[0][f][jl], pacc[1][f][jl]),
                            __fadd_rn(pacc[2][f][jl], pacc[3][f][jl]));
        dst[(size_t)f * N_EDGES + j0 + jl] = x;
    }
}

// ---------------- phase 2: mi = (Ri.*e) @ bo, mo = (Ro.*e) @ bi ----------------
// Ref semantics (confirmed): 4-lane mod-4 ascending FMA chains over j,
// term = fl32(Ri[n,j]*e[j]), combined ((l0+l1)+(l2+l3)).
// e and boT/biT staged into smem alongside A (no per-iter LDG).
#define P2_NB  32
#define P2_JT  128
__global__ void __launch_bounds__(128) phase2_kernel(const float* __restrict__ Ri,
                                                     const float* __restrict__ Ro,
                                                     const float* __restrict__ e) {
    int mat = blockIdx.x & 1;            // 0: mi (Ri, boT), 1: mo (Ro, biT)
    const float* A  = mat ? Ro : Ri;
    const float* BT = mat ? g_biT : g_boT;
    float* dst      = mat ? g_mo : g_mi;
    int n0  = (int)(blockIdx.x >> 1) * P2_NB;
    int tid = threadIdx.x;
    int f = tid & 3, nl = tid >> 2;
    int n = n0 + nl;

    __shared__ __align__(16) float tile[2][P2_NB][P2_JT + 4];
    __shared__ float4 e4t[2][P2_JT / 4];
    __shared__ float4 btt[2][4][(P2_JT / 4) + 1];   // pad 1 f4 -> f rows on distinct bank quads

    auto stage = [&](int t, int s) {
        int jt = t * P2_JT;
        const float* base = A + (size_t)n0 * N_EDGES + jt;
        #pragma unroll
        for (int o = 0; o < 8; o++) {
            int idx = o * 128 + tid;          // 1024 float4
            int row = idx >> 5, c4 = idx & 31;
            cp_async16(&tile[s][row][c4 * 4], base + (size_t)row * N_EDGES + c4 * 4);
        }
        if (tid < 32)
            cp_async16(&e4t[s][tid], e + jt + tid * 4);
        {
            int ff = tid >> 5, q = tid & 31;  // 128 threads cover 4 x 32
            cp_async16(&btt[s][ff][q], BT + (size_t)ff * N_EDGES + jt + q * 4);
        }
        cp_commit();
    };

    stage(0, 0);
    float a0 = 0.f, a1 = 0.f, a2 = 0.f, a3 = 0.f;
    const int NT = N_EDGES / P2_JT;     // 64
    for (int t = 0; t < NT; t++) {
        int s = t & 1;
        if (t + 1 < NT) { stage(t + 1, s ^ 1); cp_wait<1>(); }
        else            { cp_wait<0>(); }
        __syncthreads();
        #pragma unroll
        for (int q = 0; q < P2_JT / 4; q++) {
            float4 av = *(const float4*)&tile[s][nl][q * 4];
            float4 ev = e4t[s][q];
            float4 bv = btt[s][f][q];
            a0 = __fmaf_rn(__fmul_rn(av.x, ev.x), bv.x, a0);
            a1 = __fmaf_rn(__fmul_rn(av.y, ev.y), bv.y, a1);
            a2 = __fmaf_rn(__fmul_rn(av.z, ev.z), bv.z, a2);
            a3 = __fmaf_rn(__fmul_rn(av.w, ev.w), bv.w, a3);
        }
        __syncthreads();
    }
    float x = __fadd_rn(__fadd_rn(a0, a1), __fadd_rn(a2, a3));
    dst[n * 4 + f] = x;
}

// ---------------- circuit: 8 register-resident passes ----------------
// wire w <-> bit (11 - w). 16 (RY,RY,CX) triples pair into 8 passes over 4-bit
// (16-amplitude) groups held in registers. Smem state uses linear XOR swizzle
// phys = idx ^ ((idx>>4)&31); per-pass lane-bit placement chosen so all LDS/STS
// are bank-conflict-free. Gate arithmetic identical to the r7 FUSED version.
#define SWZ(x) ((x) ^ (((x) >> 4) & 31))
#define PAT4(p, S0,S1,S2,S3) (((((p)>>0)&1)<<(S0)) | ((((p)>>1)&1)<<(S1)) | \
                              ((((p)>>2)&1)<<(S2)) | ((((p)>>3)&1)<<(S3)))
#define LD16(S0,S1,S2,S3) { _Pragma("unroll") \
    for (int p_ = 0; p_ < 16; p_++) v[p_] = st[sb ^ SWZ(PAT4(p_,S0,S1,S2,S3))]; }
#define ST16(S0,S1,S2,S3) { _Pragma("unroll") \
    for (int p_ = 0; p_ < 16; p_++) st[sb ^ SWZ(PAT4(p_,S0,S1,S2,S3))] = v[p_]; }
#define RY16(K, TI) { const float c_ = cst[TI], s_ = snt[TI]; \
    _Pragma("unroll") for (int i_ = 0; i_ < 16; i_++) if (!((i_ >> (K)) & 1)) { \
        int i1_ = i_ | (1 << (K)); \
        float a0_ = v[i_], a1_ = v[i1_]; \
        v[i_]  = c_ * a0_ - s_ * a1_; \
        v[i1_] = s_ * a0_ + c_ * a1_; } }
#define CX16(KC, KT) { _Pragma("unroll") \
    for (int i_ = 0; i_ < 16; i_++) if (((i_ >> (KC)) & 1) && !((i_ >> (KT)) & 1)) { \
        int i1_ = i_ | (1 << (KT)); \
        float tp_ = v[i_]; v[i_] = v[i1_]; v[i1_] = tp_; } }

__global__ void __launch_bounds__(256) circuit_kernel(const float* __restrict__ X,
                                                      float* __restrict__ out) {
    __shared__ float  st[DIMQ];
    __shared__ float  cw[12], sw[12];
    __shared__ float  cst[33], snt[33];
    __shared__ double redsm[8];

    int b = blockIdx.x, tid = threadIdx.x;

    if (tid < 12) {
        float angf = (tid < 4) ? g_mi[b * 4 + tid]
                   : (tid < 8) ? g_mo[b * 4 + tid - 4]
                               : X[b * 4 + tid - 8];
        double h = 0.5 * (double)angf;   // f64 trig: exact range reduction
        cw[tid] = (float)cos(h);
        sw[tid] = (float)sin(h);
    }
    if (tid < 33) { cst[tid] = g_cs[tid]; snt[tid] = g_sn[tid]; }
    __syncthreads();

    float v[16];

    // ---- PASS 1: S={7,8,9,10} (wires 4,3,2,1)  L={0,1,2,3,4} W={5,6,11}
    // init product fused in; then T0 (ry0@1, ry1@2, cx1->2), T1 (ry2@3, ry3@4, cx4->3)
    {
        int base = (tid & 127) | (((tid >> 7) & 1) << 11);
        float pb;
        pb  = ((base >> 11) & 1) ? sw[0]  : cw[0];
        pb *= ((base >> 6)  & 1) ? sw[5]  : cw[5];
        pb *= ((base >> 5)  & 1) ? sw[6]  : cw[6];
        pb *= ((base >> 4)  & 1) ? sw[7]  : cw[7];
        pb *= ((base >> 3)  & 1) ? sw[8]  : cw[8];
        pb *= ((base >> 2)  & 1) ? sw[9]  : cw[9];
        pb *= ((base >> 1)  & 1) ? sw[10] : cw[10];
        pb *= ((base >> 0)  & 1) ? sw[11] : cw[11];
        float f40 = cw[4], f41 = sw[4], f30 = cw[3], f31 = sw[3];
        float f20 = cw[2], f21 = sw[2], f10 = cw[1], f11 = sw[1];
        #pragma unroll
        for (int p = 0; p < 16; p++)
            v[p] = pb * ((p & 1) ? f41 : f40) * ((p & 2) ? f31 : f30)
                      * ((p & 4) ? f21 : f20) * ((p & 8) ? f11 : f10);
        RY16(3, 0)  RY16(2, 1)  CX16(3, 2)      // T0
        RY16(1, 2)  RY16(0, 3)  CX16(0, 1)      // T1
        int sb = SWZ(base);
        ST16(7, 8, 9, 10)
    }
    __syncthreads();

    // ---- PASS 2: S={3,4,5,6} (wires 8,7,6,5)  L={0,1,2,7,8} W={9,10,11}
    {
        int base = (tid & 7) | (((tid >> 3) & 31) << 7);
        int sb = SWZ(base);
        LD16(3, 4, 5, 6)
        RY16(3, 4)  RY16(2, 5)  CX16(3, 2)      // T2: cx5->6
        RY16(1, 6)  RY16(0, 7)  CX16(1, 0)      // T3: cx7->8
        ST16(3, 4, 5, 6)
    }
    __syncthreads();

    // ---- PASS 3: S={1,2,10,11} (wires 10,9,1,0)  L={0,3,4,5,6} W={7,8,9}
    {
        int base = (tid & 1) | (((tid >> 1) & 15) << 3) | (((tid >> 5) & 7) << 7);
        int sb = SWZ(base);
        LD16(1, 2, 10, 11)
        RY16(1, 8)  RY16(0, 9)  CX16(0, 1)      // T4: cx10->9
        RY16(3, 10) RY16(2, 11) CX16(3, 2)      // T5: cx0->1
        ST16(1, 2, 10, 11)
    }
    __syncthreads();

    // ---- PASS 4: S={6,7,8,9} (wires 5,4,3,2)  L={0,1,2,3,4} W={5,10,11}
    {
        int base = (tid & 31) | (((tid >> 5) & 1) << 5) | (((tid >> 6) & 3) << 10);
        int sb = SWZ(base);
        LD16(6, 7, 8, 9)
        RY16(3, 12) RY16(2, 13) CX16(2, 3)      // T6: cx3->2
        RY16(1, 14) RY16(0, 15) CX16(1, 0)      // T7: cx4->5
        ST16(6, 7, 8, 9)
    }
    __syncthreads();

    // ---- PASS 5: S={2,3,4,5} (wires 9,8,7,6)  L={0,1,6,7,8} W={9,10,11}
    {
        int base = (tid & 3) | (((tid >> 2) & 7) << 6) | (((tid >> 5) & 7) << 9);
        int sb = SWZ(base);
        LD16(2, 3, 4, 5)
        RY16(3, 16) RY16(2, 17) CX16(2, 3)      // T8: cx7->6
        RY16(1, 18) RY16(0, 19) CX16(1, 0)      // T9: cx8->9
        ST16(2, 3, 4, 5)
    }
    __syncthreads();

    // ---- PASS 6: S={0,1,6,9} (wires 11,10,5,2)  L={2,3,4,5,8} W={7,10,11}
    {
        int base = ((tid & 15) << 2) | (((tid >> 4) & 1) << 8)
                 | (((tid >> 5) & 1) << 7) | (((tid >> 6) & 3) << 10);
        int sb = SWZ(base);
        LD16(0, 1, 6, 9)
        RY16(1, 20) RY16(0, 21) CX16(0, 1)      // T10: cx11->10
        RY16(3, 22) RY16(2, 23) CX16(2, 3)      // T11: cx5->2
        ST16(0, 1, 6, 9)
    }
    __syncthreads();

    // ---- PASS 7: S={2,5,9,10} (wires 9,6,2,1)  L={0,1,3,4,6} W={7,8,11}
    {
        int base = (tid & 3) | (((tid >> 2) & 3) << 3) | (((tid >> 4) & 1) << 6)
                 | (((tid >> 5) & 3) << 7) | (((tid >> 7) & 1) << 11);
        int sb = SWZ(base);
        LD16(2, 5, 9, 10)
        RY16(1, 24) RY16(0, 25) CX16(1, 0)      // T12: cx6->9
        RY16(3, 26) RY16(2, 27) CX16(3, 2)      // T13: cx1->2
        ST16(2, 5, 9, 10)
    }
    __syncthreads();

    // ---- PASS 8: S={0,1,2,9} (wires 11,10,9,2)  L={3,4,5,6,8} W={7,10,11}
    // T14, T15, final RY(32@9), and the expz reduction (logical bit2 = slot 2)
    float local = 0.0f;
    {
        int base = ((tid & 15) << 3) | (((tid >> 4) & 1) << 8)
                 | (((tid >> 5) & 1) << 7) | (((tid >> 6) & 3) << 10);
        int sb = SWZ(base);
        LD16(0, 1, 2, 9)
        RY16(2, 28) RY16(1, 29) CX16(1, 2)      // T14: cx10->9
        RY16(3, 30) RY16(2, 31) CX16(3, 2)      // T15: cx2->9
        RY16(2, 32)                              // final ry@9
        #pragma unroll
        for (int p = 0; p < 16; p++) {
            float v2 = v[p] * v[p];
            local += (p & 4) ? -v2 : v2;
        }
    }

    double dv = (double)local;
    #pragma unroll
    for (int o = 16; o > 0; o >>= 1) dv += __shfl_down_sync(0xffffffffu, dv, o);
    int lane = tid & 31, wp = tid >> 5;
    if (lane == 0) redsm[wp] = dv;
    __syncthreads();
    if (tid == 0) {
        double expz = 0.0;
        for (int w = 0; w < 8; w++) expz += redsm[w];
        out[b] = (float)(1.5707963267948966 * (1.0 - expz));
    }
}

// ---------------- launch ----------------
extern "C" void kernel_launch(void* const* d_in, const int* in_sizes, int n_in,
                              void* d_out, int out_size) {
    const float *X = 0, *e = 0, *Ri = 0, *Ro = 0, *th = 0;
    for (int i = 0; i < n_in; i++) {
        int s = in_sizes[i];
        const float* p = (const float*)d_in[i];
        if (s == N_NODES * 4)            X = p;
        else if (s == N_EDGES)           e = p;
        else if (s == 33)                th = p;
        else if (s == N_NODES * N_EDGES) { if (!Ri) Ri = p; else Ro = p; }
    }
    float* out = (float*)d_out;

    init_kernel<<<1, 64>>>(th);
    phase1_kernel<<<(N_EDGES / P1_BJ) * 2, 128>>>(Ri, Ro, X);
    phase2_kernel<<<(N_NODES / P2_NB) * 2, 128>>>(Ri, Ro, e);
    circuit_kernel<<<N_NODES, 256>>>(X, out);
}